// round 15
// baseline (speedup 1.0000x reference)
#include <cuda_runtime.h>

#define N_NODES 20000
#define N_EDGES 320000
#define DIM_D   768
#define DIM_H   1024
#define SDIM    2000
#define VB      (DIM_D + 1)              // blocks for v/s1 computation
#define E4      (N_EDGES / 4)            // edge quads
#define EB4     ((E4 + 255) / 256)       // 313 blocks
#define ZB      ((N_NODES + 7) / 8)      // k_z blocks (8 warps each)

// ---- scratch (static __device__ globals; zero-initialized at module load) ----
__device__ float  g_v[DIM_D];      // W1 @ W2
__device__ float  g_s1;            // b1 . W2
__device__ float4 g_node[N_NODES]; // {x=deg, y=z, z=p, w=p2}
                                   // .x re-zeroed by k_selmask each run (replay-safe)
__device__ float  g_cutoff;

// Shared formulas (deg -> dinv on the fly; deterministic rsqrtf).
__device__ __forceinline__ float node_di(float4 gi) { return rsqrtf(gi.x + 1.0f); }
__device__ __forceinline__ float node_q2(float4 gi, float s1) {
    float di = node_di(gi);
    return di * (di * (gi.z + di * gi.y) + s1);
}

// ---------------------------------------------------------------------------
// v[d] = W1[d,:].W2 (block DIM_D: s1 = b1.W2)
__global__ void k_v(const float* __restrict__ W1, const float* __restrict__ W2,
                    const float* __restrict__ b1) {
    int d = blockIdx.x;
    const float* rowp = (d < DIM_D) ? (W1 + (size_t)d * DIM_H) : b1;
    const float4* rp = (const float4*)rowp;
    const float4* w2 = (const float4*)W2;
    float s = 0.f;
    int lane = threadIdx.x & 31;
    int warp = threadIdx.x >> 5;
    for (int i = threadIdx.x; i < DIM_H / 4; i += 256)
        { float4 a = rp[i]; float4 b = w2[i];
          s += a.x * b.x + a.y * b.y + a.z * b.z + a.w * b.w; }
    #pragma unroll
    for (int o = 16; o; o >>= 1) s += __shfl_xor_sync(0xffffffffu, s, o);
    __shared__ float red[8];
    if (!lane) red[warp] = s;
    __syncthreads();
    if (threadIdx.x == 0) {
        float t = 0.f;
        #pragma unroll
        for (int w = 0; w < 8; w++) t += red[w];
        if (d < DIM_D) g_v[d] = t; else g_s1 = t;
    }
}

// ---------------------------------------------------------------------------
// One warp per node: z = x[n,:].v stored to node.y; .z/.w zeroed (scalar
// stores -- .x holds concurrent deg atomics).
// Side-work: deg scatter (4 edges/thread on the first E4 global threads),
// hidden inside this DRAM-bound sweep's spare issue slots.
__global__ void k_z(const float* __restrict__ x,
                    const int* __restrict__ col, const float* __restrict__ ew) {
    // deg side-work first: its DRAM loads overlap the x stream below
    int g = blockIdx.x * blockDim.x + threadIdx.x;
    if (g < E4) {
        int4   c = ((const int4*)col)[g];
        float4 w = ((const float4*)ew)[g];
        float* nf = (float*)g_node;
        atomicAdd(&nf[4 * c.x], w.x);
        atomicAdd(&nf[4 * c.y], w.y);
        atomicAdd(&nf[4 * c.z], w.z);
        atomicAdd(&nf[4 * c.w], w.w);
    }
    __shared__ float sv[DIM_D];
    for (int i = threadIdx.x; i < DIM_D; i += blockDim.x) sv[i] = g_v[i];
    __syncthreads();
    int warp = threadIdx.x >> 5, lane = threadIdx.x & 31;
    int n = blockIdx.x * (blockDim.x >> 5) + warp;
    if (n >= N_NODES) return;
    const float4* xr = (const float4*)(x + (size_t)n * DIM_D);
    const float4* vv = (const float4*)sv;
    float sum = 0.f;
    #pragma unroll
    for (int i = lane; i < DIM_D / 4; i += 32) {
        float4 a = __ldcs(&xr[i]);      // streaming: keep edges/node L2-resident
        float4 b = vv[i];
        sum += a.x * b.x + a.y * b.y + a.z * b.z + a.w * b.w;
    }
    #pragma unroll
    for (int o = 16; o; o >>= 1) sum += __shfl_xor_sync(0xffffffffu, sum, o);
    if (!lane) {
        float* nf = (float*)&g_node[n];
        nf[1] = sum;                      // z
        *(float2*)&nf[2] = make_float2(0.f, 0.f);   // p, p2
    }
}

// ---------------------------------------------------------------------------
// p[c] += w * q[r],  q = rsqrt(deg+1)*z  (4 edges/thread, 8B {deg,z} gather)
__global__ void k_edge1(const int* __restrict__ row, const int* __restrict__ col,
                        const float* __restrict__ ew) {
    int i = blockIdx.x * blockDim.x + threadIdx.x;
    if (i >= E4) return;
    int4   r = ((const int4*)row)[i];
    int4   c = ((const int4*)col)[i];
    float4 w = ((const float4*)ew)[i];
    const float2* n2 = (const float2*)g_node;   // [2*n] = {deg, z}
    float* nf = (float*)g_node;
    float2 g0 = n2[2 * r.x];
    float2 g1 = n2[2 * r.y];
    float2 g2 = n2[2 * r.z];
    float2 g3 = n2[2 * r.w];
    float a0 = w.x * rsqrtf(g0.x + 1.0f) * g0.y;
    float a1 = w.y * rsqrtf(g1.x + 1.0f) * g1.y;
    float a2 = w.z * rsqrtf(g2.x + 1.0f) * g2.y;
    float a3 = w.w * rsqrtf(g3.x + 1.0f) * g3.y;
    atomicAdd(&nf[4 * c.x + 2], a0);
    atomicAdd(&nf[4 * c.y + 2], a1);
    atomicAdd(&nf[4 * c.z + 2], a2);
    atomicAdd(&nf[4 * c.w + 2], a3);
}

// ---------------------------------------------------------------------------
// p2[c] += w * q2[r]   (4 edges/thread; one 16B gather per edge)
__global__ void k_edge2(const int* __restrict__ row, const int* __restrict__ col,
                        const float* __restrict__ ew) {
    int i = blockIdx.x * blockDim.x + threadIdx.x;
    if (i >= E4) return;
    float s1 = g_s1;
    int4   r = ((const int4*)row)[i];
    int4   c = ((const int4*)col)[i];
    float4 w = ((const float4*)ew)[i];
    float* nf = (float*)g_node;
    float a0 = w.x * node_q2(g_node[r.x], s1);
    float a1 = w.y * node_q2(g_node[r.y], s1);
    float a2 = w.z * node_q2(g_node[r.z], s1);
    float a3 = w.w * node_q2(g_node[r.w], s1);
    atomicAdd(&nf[4 * c.x + 3], a0);
    atomicAdd(&nf[4 * c.y + 3], a1);
    atomicAdd(&nf[4 * c.z + 3], a2);
    atomicAdd(&nf[4 * c.w + 3], a3);
}

// ---------------------------------------------------------------------------
// Single block: att; k = count(y>=0); cutoff = k-th largest of att[:S]; loss;
// then the SAME block writes the full mask (n<S from the exact shared values)
// and re-zeroes node.x (deg) for the next replay.
__global__ void k_selmask(const int* __restrict__ y, const float* __restrict__ b2,
                          float* __restrict__ out, int off, int write_loss) {
    __shared__ float s_val[SDIM];
    __shared__ float s_t[SDIM];
    __shared__ int   s_k;
    __shared__ float s_rv[32];
    __shared__ int   s_ri[32];
    __shared__ float s_cut;
    int tid = threadIdx.x;
    if (tid == 0) s_k = 0;
    float bb = b2[0];
    float s1 = g_s1;
    for (int i = tid; i < SDIM; i += 1024) {
        float4 gi = g_node[i];
        float a = node_di(gi) * (gi.w + node_q2(gi, s1)) + bb;
        s_val[i] = a;
        s_t[i] = 0.f;
    }
    __syncthreads();

    int kc = 0;
    for (int j = tid; j < SDIM; j += 1024) {
        int yy = y[j];
        kc += (yy >= 0);
        if (yy > 0) s_t[yy] = 1.0f;   // idempotent; races benign
    }
    #pragma unroll
    for (int o = 16; o; o >>= 1) kc += __shfl_xor_sync(0xffffffffu, kc, o);
    if ((tid & 31) == 0) atomicAdd(&s_k, kc);
    __syncthreads();
    int k = max(s_k, 1);

    // loss accumulation BEFORE destructive selection; keep att copy in regs
    float av0 = s_val[tid];
    float av1 = (tid + 1024 < SDIM) ? s_val[tid + 1024] : 0.f;
    float acc = 0.f;
    for (int j = tid; j < SDIM; j += 1024) {
        float v = s_val[j], t = s_t[j];
        float lp = log1pf(expf(-fabsf(v)));
        acc += t * (fminf(v, 0.f) - lp) + (1.f - t) * (fminf(-v, 0.f) - lp);
    }

    // k iterative (val, idx) argmax; remove one instance per round
    for (int it = 0; it < k; it++) {
        float bv = -3.4e38f;
        int   bi = SDIM;
        for (int j = tid; j < SDIM; j += 1024) {
            float v = s_val[j];
            if (v > bv) { bv = v; bi = j; }
        }
        #pragma unroll
        for (int o = 16; o; o >>= 1) {
            float ov = __shfl_xor_sync(0xffffffffu, bv, o);
            int   oi = __shfl_xor_sync(0xffffffffu, bi, o);
            if (ov > bv || (ov == bv && oi < bi)) { bv = ov; bi = oi; }
        }
        if ((tid & 31) == 0) { s_rv[tid >> 5] = bv; s_ri[tid >> 5] = bi; }
        __syncthreads();
        if (tid < 32) {
            bv = s_rv[tid]; bi = s_ri[tid];
            #pragma unroll
            for (int o = 16; o; o >>= 1) {
                float ov = __shfl_xor_sync(0xffffffffu, bv, o);
                int   oi = __shfl_xor_sync(0xffffffffu, bi, o);
                if (ov > bv || (ov == bv && oi < bi)) { bv = ov; bi = oi; }
            }
            if (tid == 0) { s_cut = bv; s_val[bi] = -3.4e38f; }
        }
        __syncthreads();
    }

    // loss reduction
    #pragma unroll
    for (int o = 16; o; o >>= 1) acc += __shfl_xor_sync(0xffffffffu, acc, o);
    if ((tid & 31) == 0) s_rv[tid >> 5] = acc;
    __syncthreads();
    if (tid == 0) {
        if (write_loss) {
            float tot = 0.f;
            #pragma unroll
            for (int w = 0; w < 32; w++) tot += s_rv[w];
            out[0] = -tot / (float)SDIM;
        }
        g_cutoff = s_cut;   // kept for debuggability
    }
    __syncthreads();
    float cut = s_cut;

    // mask write for ALL nodes + replay re-zero of node.x (deg)
    // n < SDIM: use the exact att values the cutoff was derived from.
    out[off + tid] = (av0 >= cut) ? 1.0f : 0.0f;
    if (tid + 1024 < SDIM)
        out[off + tid + 1024] = (av1 >= cut) ? 1.0f : 0.0f;
    float* nf = (float*)g_node;
    for (int n = tid; n < SDIM; n += 1024) nf[4 * n] = 0.f;
    for (int n = SDIM + tid; n < N_NODES; n += 1024) {
        float4 gi = g_node[n];
        float a = node_di(gi) * (gi.w + node_q2(gi, s1)) + bb;
        out[off + n] = (a >= cut) ? 1.0f : 0.0f;
        nf[4 * n] = 0.f;
    }
}

// ---------------------------------------------------------------------------
extern "C" void kernel_launch(void* const* d_in, const int* in_sizes, int n_in,
                              void* d_out, int out_size) {
    const float* x  = (const float*)d_in[0];
    const int*   ei = (const int*)d_in[1];
    const float* ew = (const float*)d_in[2];
    const int*   y  = (const int*)d_in[3];
    const float* W1 = (const float*)d_in[4];
    const float* b1 = (const float*)d_in[5];
    const float* W2 = (const float*)d_in[6];
    const float* b2 = (const float*)d_in[7];
    const int* row = ei;             // edge_index[0,:]
    const int* col = ei + N_EDGES;   // edge_index[1,:]
    float* out = (float*)d_out;
    int off = (out_size > N_NODES) ? (out_size - N_NODES) : 0;  // expect 1

    k_v<<<VB, 256>>>(W1, W2, b1);
    k_z<<<ZB, 256>>>(x, col, ew);
    k_edge1<<<EB4, 256>>>(row, col, ew);
    k_edge2<<<EB4, 256>>>(row, col, ew);
    k_selmask<<<1, 1024>>>(y, b2, out, off, off >= 1 ? 1 : 0);
}

// round 16
// speedup vs baseline: 1.1101x; 1.1101x over previous
#include <cuda_runtime.h>

#define N_NODES 20000
#define N_EDGES 320000
#define DIM_D   768
#define DIM_H   1024
#define SDIM    2000
#define VB      (DIM_D + 1)              // blocks for v/s1 computation
#define E4      (N_EDGES / 4)            // edge quads
#define EB4     ((E4 + 255) / 256)       // 313 blocks
#define ZB      ((N_NODES + 7) / 8)      // k_z blocks (8 warps each)
#define NB      ((N_NODES + 255) / 256)

// ---- scratch (static __device__ globals; zero-initialized at module load) ----
__device__ float  g_v[DIM_D];      // W1 @ W2
__device__ float  g_s1;            // b1 . W2
__device__ float4 g_node[N_NODES]; // {x=deg, y=z, z=p, w=p2}
                                   // .x re-zeroed by k_mask each run (replay-safe)
__device__ float  g_att_s[SDIM];   // att[0:S) exactly as k_select saw them
__device__ float  g_cutoff;

// deg -> dinv on the fly (deterministic rsqrtf); shared by all consumers.
__device__ __forceinline__ float node_di(float4 gi) { return rsqrtf(gi.x + 1.0f); }
__device__ __forceinline__ float node_q2(float4 gi, float s1) {
    float di = node_di(gi);
    return di * (di * (gi.z + di * gi.y) + s1);
}

__device__ __forceinline__ void prefetch_l2(const void* p) {
    asm volatile("prefetch.global.L2 [%0];" :: "l"(p));
}

// ---------------------------------------------------------------------------
// v[d] = W1[d,:].W2 (block DIM_D: s1 = b1.W2)
__global__ void k_v(const float* __restrict__ W1, const float* __restrict__ W2,
                    const float* __restrict__ b1) {
    int d = blockIdx.x;
    const float* rowp = (d < DIM_D) ? (W1 + (size_t)d * DIM_H) : b1;
    const float4* rp = (const float4*)rowp;
    const float4* w2 = (const float4*)W2;
    float s = 0.f;
    int lane = threadIdx.x & 31;
    int warp = threadIdx.x >> 5;
    for (int i = threadIdx.x; i < DIM_H / 4; i += 256)
        { float4 a = rp[i]; float4 b = w2[i];
          s += a.x * b.x + a.y * b.y + a.z * b.z + a.w * b.w; }
    #pragma unroll
    for (int o = 16; o; o >>= 1) s += __shfl_xor_sync(0xffffffffu, s, o);
    __shared__ float red[8];
    if (!lane) red[warp] = s;
    __syncthreads();
    if (threadIdx.x == 0) {
        float t = 0.f;
        #pragma unroll
        for (int w = 0; w < 8; w++) t += red[w];
        if (d < DIM_D) g_v[d] = t; else g_s1 = t;
    }
}

// ---------------------------------------------------------------------------
// One warp per node: node.y = z = x[n,:].v; zero .z/.w. Does NOT touch .x
// (deg, zeroed by previous run's k_mask, scattered by k_deg AFTER this).
// Runs BEFORE the edge-array warm-up so the 61MB x stream can't evict edges.
__global__ void k_z(const float* __restrict__ x) {
    __shared__ float sv[DIM_D];
    for (int i = threadIdx.x; i < DIM_D; i += blockDim.x) sv[i] = g_v[i];
    __syncthreads();
    int warp = threadIdx.x >> 5, lane = threadIdx.x & 31;
    int n = blockIdx.x * (blockDim.x >> 5) + warp;
    if (n >= N_NODES) return;
    const float4* xr = (const float4*)(x + (size_t)n * DIM_D);
    const float4* vv = (const float4*)sv;
    float sum = 0.f;
    #pragma unroll
    for (int i = lane; i < DIM_D / 4; i += 32) {
        float4 a = __ldcs(&xr[i]);      // streaming hint
        float4 b = vv[i];
        sum += a.x * b.x + a.y * b.y + a.z * b.z + a.w * b.w;
    }
    #pragma unroll
    for (int o = 16; o; o >>= 1) sum += __shfl_xor_sync(0xffffffffu, sum, o);
    if (!lane) {
        float* nf = (float*)&g_node[n];
        nf[1] = sum;                                 // z
        *(float2*)&nf[2] = make_float2(0.f, 0.f);    // p, p2
    }
}

// ---------------------------------------------------------------------------
// deg scatter into node.x (4 edges/thread). Runs right before the edge
// kernels: demand-loads col/ew and prefetches row so all three edge streams
// are L2-resident for edge1/edge2 with nothing in between to evict them.
__global__ void k_deg(const int* __restrict__ row, const int* __restrict__ col,
                      const float* __restrict__ ew) {
    int i = blockIdx.x * blockDim.x + threadIdx.x;
    if (i >= E4) return;
    if ((i & 7) == 0) prefetch_l2(&row[4 * i]);   // one 128B line per 8 quads
    int4   c = ((const int4*)col)[i];
    float4 w = ((const float4*)ew)[i];
    float* nf = (float*)g_node;
    atomicAdd(&nf[4 * c.x], w.x);
    atomicAdd(&nf[4 * c.y], w.y);
    atomicAdd(&nf[4 * c.z], w.z);
    atomicAdd(&nf[4 * c.w], w.w);
}

// ---------------------------------------------------------------------------
// p[c] += w * q[r],  q = rsqrt(deg+1)*z   (4 edges/thread, 8B {deg,z} gather)
__global__ void k_edge1(const int* __restrict__ row, const int* __restrict__ col,
                        const float* __restrict__ ew) {
    int i = blockIdx.x * blockDim.x + threadIdx.x;
    if (i >= E4) return;
    int4   r = ((const int4*)row)[i];
    int4   c = ((const int4*)col)[i];
    float4 w = ((const float4*)ew)[i];
    const float2* n2 = (const float2*)g_node;   // [2*n] = {deg, z}
    float* nf = (float*)g_node;
    float2 g0 = n2[2 * r.x];
    float2 g1 = n2[2 * r.y];
    float2 g2 = n2[2 * r.z];
    float2 g3 = n2[2 * r.w];
    float a0 = w.x * rsqrtf(g0.x + 1.0f) * g0.y;
    float a1 = w.y * rsqrtf(g1.x + 1.0f) * g1.y;
    float a2 = w.z * rsqrtf(g2.x + 1.0f) * g2.y;
    float a3 = w.w * rsqrtf(g3.x + 1.0f) * g3.y;
    atomicAdd(&nf[4 * c.x + 2], a0);
    atomicAdd(&nf[4 * c.y + 2], a1);
    atomicAdd(&nf[4 * c.z + 2], a2);
    atomicAdd(&nf[4 * c.w + 2], a3);
}

// ---------------------------------------------------------------------------
// p2[c] += w * q2[r]   (4 edges/thread; one 16B gather per edge)
__global__ void k_edge2(const int* __restrict__ row, const int* __restrict__ col,
                        const float* __restrict__ ew) {
    int i = blockIdx.x * blockDim.x + threadIdx.x;
    if (i >= E4) return;
    float s1 = g_s1;
    int4   r = ((const int4*)row)[i];
    int4   c = ((const int4*)col)[i];
    float4 w = ((const float4*)ew)[i];
    float* nf = (float*)g_node;
    float a0 = w.x * node_q2(g_node[r.x], s1);
    float a1 = w.y * node_q2(g_node[r.y], s1);
    float a2 = w.z * node_q2(g_node[r.z], s1);
    float a3 = w.w * node_q2(g_node[r.w], s1);
    atomicAdd(&nf[4 * c.x + 3], a0);
    atomicAdd(&nf[4 * c.y + 3], a1);
    atomicAdd(&nf[4 * c.z + 3], a2);
    atomicAdd(&nf[4 * c.w + 3], a3);
}

// ---------------------------------------------------------------------------
// att[n] = dinv*(p2 + q2) + b2.
// Single block: k = count(y>=0); cutoff = k-th largest of att[:S]; loss.
__global__ void k_select(const int* __restrict__ y, const float* __restrict__ b2,
                         float* __restrict__ out, int write_loss) {
    __shared__ float s_val[SDIM];
    __shared__ float s_t[SDIM];
    __shared__ int   s_k;
    __shared__ float s_rv[32];
    __shared__ int   s_ri[32];
    __shared__ float s_cut;
    int tid = threadIdx.x;
    if (tid == 0) s_k = 0;
    float bb = b2[0];
    float s1 = g_s1;
    for (int i = tid; i < SDIM; i += 1024) {
        float4 gi = g_node[i];
        float a = node_di(gi) * (gi.w + node_q2(gi, s1)) + bb;
        s_val[i] = a;
        g_att_s[i] = a;           // exact bits reused by k_mask
        s_t[i] = 0.f;
    }
    __syncthreads();

    int kc = 0;
    for (int j = tid; j < SDIM; j += 1024) {
        int yy = y[j];
        kc += (yy >= 0);
        if (yy > 0) s_t[yy] = 1.0f;   // idempotent; races benign
    }
    #pragma unroll
    for (int o = 16; o; o >>= 1) kc += __shfl_xor_sync(0xffffffffu, kc, o);
    if ((tid & 31) == 0) atomicAdd(&s_k, kc);
    __syncthreads();
    int k = max(s_k, 1);

    // loss accumulation BEFORE destructive selection
    float acc = 0.f;
    for (int j = tid; j < SDIM; j += 1024) {
        float v = s_val[j], t = s_t[j];
        float lp = log1pf(expf(-fabsf(v)));
        acc += t * (fminf(v, 0.f) - lp) + (1.f - t) * (fminf(-v, 0.f) - lp);
    }

    // k iterative (val, idx) argmax; remove one instance per round
    for (int it = 0; it < k; it++) {
        float bv = -3.4e38f;
        int   bi = SDIM;
        for (int j = tid; j < SDIM; j += 1024) {
            float v = s_val[j];
            if (v > bv) { bv = v; bi = j; }
        }
        #pragma unroll
        for (int o = 16; o; o >>= 1) {
            float ov = __shfl_xor_sync(0xffffffffu, bv, o);
            int   oi = __shfl_xor_sync(0xffffffffu, bi, o);
            if (ov > bv || (ov == bv && oi < bi)) { bv = ov; bi = oi; }
        }
        if ((tid & 31) == 0) { s_rv[tid >> 5] = bv; s_ri[tid >> 5] = bi; }
        __syncthreads();
        if (tid < 32) {
            bv = s_rv[tid]; bi = s_ri[tid];
            #pragma unroll
            for (int o = 16; o; o >>= 1) {
                float ov = __shfl_xor_sync(0xffffffffu, bv, o);
                int   oi = __shfl_xor_sync(0xffffffffu, bi, o);
                if (ov > bv || (ov == bv && oi < bi)) { bv = ov; bi = oi; }
            }
            if (tid == 0) { s_cut = bv; s_val[bi] = -3.4e38f; }
        }
        __syncthreads();
    }
    if (tid == 0) g_cutoff = s_cut;

    // loss reduction
    #pragma unroll
    for (int o = 16; o; o >>= 1) acc += __shfl_xor_sync(0xffffffffu, acc, o);
    if ((tid & 31) == 0) s_rv[tid >> 5] = acc;
    __syncthreads();
    if (tid == 0 && write_loss) {
        float tot = 0.f;
        #pragma unroll
        for (int w = 0; w < 32; w++) tot += s_rv[w];
        out[0] = -tot / (float)SDIM;
    }
}

// ---------------------------------------------------------------------------
// parallel mask write; side work: re-zero node.x (deg) for the next replay
__global__ void k_mask(const float* __restrict__ b2, float* __restrict__ out, int off) {
    int n = blockIdx.x * blockDim.x + threadIdx.x;
    if (n >= N_NODES) return;
    float a;
    if (n < SDIM) {
        a = g_att_s[n];                      // identical bits to k_select
    } else {
        float4 gi = g_node[n];
        a = node_di(gi) * (gi.w + node_q2(gi, g_s1)) + b2[0];
    }
    out[off + n] = (a >= g_cutoff) ? 1.0f : 0.0f;
    ((float*)g_node)[4 * n] = 0.f;           // deg = 0 for next run
}

// ---------------------------------------------------------------------------
extern "C" void kernel_launch(void* const* d_in, const int* in_sizes, int n_in,
                              void* d_out, int out_size) {
    const float* x  = (const float*)d_in[0];
    const int*   ei = (const int*)d_in[1];
    const float* ew = (const float*)d_in[2];
    const int*   y  = (const int*)d_in[3];
    const float* W1 = (const float*)d_in[4];
    const float* b1 = (const float*)d_in[5];
    const float* W2 = (const float*)d_in[6];
    const float* b2 = (const float*)d_in[7];
    const int* row = ei;             // edge_index[0,:]
    const int* col = ei + N_EDGES;   // edge_index[1,:]
    float* out = (float*)d_out;
    int off = (out_size > N_NODES) ? (out_size - N_NODES) : 0;  // expect 1

    k_v<<<VB, 256>>>(W1, W2, b1);
    k_z<<<ZB, 256>>>(x);
    k_deg<<<EB4, 256>>>(row, col, ew);
    k_edge1<<<EB4, 256>>>(row, col, ew);
    k_edge2<<<EB4, 256>>>(row, col, ew);
    k_select<<<1, 1024>>>(y, b2, out, off >= 1 ? 1 : 0);
    k_mask<<<NB, 256>>>(b2, out, off);
}